// round 14
// baseline (speedup 1.0000x reference)
#include <cuda_runtime.h>
#include <cuda_fp16.h>
#include <cstdint>

// ---------------------------------------------------------------------------
// Model constants
// ---------------------------------------------------------------------------
#define BATCH     8
#define SEQ       512
#define INPUT_DIM 32
#define DMODEL    256
#define NLAYERS   4
#define DSTATE    16
#define DCONV     4
#define DINNER    512
#define DTRANK    16
#define MROWS     (BATCH*SEQ)    // 4096
#define LN_EPS    1e-5f
#define GRID      256
#define NTHREADS  256

// ---------------------------------------------------------------------------
// Device scratch
// ---------------------------------------------------------------------------
__device__ float  g_h   [MROWS * DMODEL];
__device__ __half g_xnh [MROWS * DMODEL];
__device__ float  g_xz  [MROWS * 2 * DINNER];
__device__ float  g_u   [MROWS * DINNER];
__device__ __half g_uh  [MROWS * DINNER];
__device__ float  g_dbl [MROWS * 48];
__device__ float  g_dt  [MROWS * DINNER];
__device__ __half g_yh  [MROWS * DINNER];
__device__ float  g_part[2 * MROWS * DMODEL];

// half scratch (offsets in halves)
#define X_H    0
#define IPW_H  131072
#define INW_H  139264
#define XPW_H  1187840
#define OPW_H  1286144
#define WH_TOTAL 1810432
__device__ __half g_wh[WH_TOTAL];

// grid barrier state
__device__ int g_bcount = 0;
__device__ volatile unsigned g_bgen = 0;

// ---------------------------------------------------------------------------
// PTX helpers
// ---------------------------------------------------------------------------
__device__ __forceinline__ void mma_f16(float* cc, const uint32_t* a, const uint32_t* b) {
    asm volatile("mma.sync.aligned.m16n8k16.row.col.f32.f16.f16.f32 "
                 "{%0,%1,%2,%3}, {%4,%5,%6,%7}, {%8,%9}, {%0,%1,%2,%3};"
                 : "+f"(cc[0]), "+f"(cc[1]), "+f"(cc[2]), "+f"(cc[3])
                 : "r"(a[0]), "r"(a[1]), "r"(a[2]), "r"(a[3]),
                   "r"(b[0]), "r"(b[1]));
}

__device__ __forceinline__ uint32_t smem_u32(const void* p) {
    uint32_t a;
    asm("{ .reg .u64 t; cvta.to.shared.u64 t, %1; cvt.u32.u64 %0, t; }"
        : "=r"(a) : "l"(p));
    return a;
}

__device__ __forceinline__ void cpasync16(uint32_t dst, const void* src, int src_sz) {
    asm volatile("cp.async.cg.shared.global [%0], [%1], 16, %2;"
                 :: "r"(dst), "l"(src), "r"(src_sz) : "memory");
}
#define CP_COMMIT()  asm volatile("cp.async.commit_group;" ::: "memory")
#define CP_WAIT(n)   asm volatile("cp.async.wait_group %0;" :: "n"(n) : "memory")

// software grid barrier (all GRID CTAs co-resident by __launch_bounds__(256,2))
__device__ __forceinline__ void gbar() {
    __syncthreads();
    if (threadIdx.x == 0) {
        const unsigned gen = g_bgen;
        __threadfence();
        if (atomicAdd(&g_bcount, 1) == GRID - 1) {
            g_bcount = 0;
            __threadfence();
            g_bgen = gen + 1;
        } else {
            while (g_bgen == gen) { }
        }
        __threadfence();
    }
    __syncthreads();
}

// ---------------------------------------------------------------------------
// Args
// ---------------------------------------------------------------------------
struct MegaArgs {
    const float *x, *ipw, *ipb, *lnw, *lnb, *inw, *cw, *cb, *xpw,
                *dtw, *dtb, *alog, *dvec, *opw, *hw1, *hb1, *hw2, *hb2;
    float *out;
    float *h, *xz, *u, *dbl, *dt, *part;
    __half *xnh, *uh, *yh, *wh;
};

// ---------------------------------------------------------------------------
// Phase: fp32 -> fp16 conversion of inputs/weights
// ---------------------------------------------------------------------------
__device__ void cvt_phase(const MegaArgs& A)
{
    const int tid = threadIdx.x;
    for (int i = (blockIdx.x * NTHREADS + tid) * 8; i < WH_TOTAL;
         i += GRID * NTHREADS * 8) {
        const float* src;
        int off;
        if      (i < IPW_H) { src = A.x;   off = i - X_H;   }
        else if (i < INW_H) { src = A.ipw; off = i - IPW_H; }
        else if (i < XPW_H) { src = A.inw; off = i - INW_H; }
        else if (i < OPW_H) { src = A.xpw; off = i - XPW_H; }
        else                { src = A.opw; off = i - OPW_H; }
        float4 v0 = *(const float4*)(src + off);
        float4 v1 = *(const float4*)(src + off + 4);
        __half2* d2 = (__half2*)(A.wh + i);
        d2[0] = __floats2half2_rn(v0.x, v0.y);
        d2[1] = __floats2half2_rn(v0.z, v0.w);
        d2[2] = __floats2half2_rn(v1.x, v1.y);
        d2[3] = __floats2half2_rn(v1.z, v1.w);
    }
}

// ---------------------------------------------------------------------------
// Phase: fp16 mma GEMM, BK=32 double-buffered (R13-proven body, tile loop)
// ---------------------------------------------------------------------------
#define BM 128
#define BN 128
#define BKH 32
#define SLDH 40
#define STAGE_H (BM * SLDH)   // 5120 halves

__device__ void gemm_phase(char* sm,
                           const __half* __restrict__ Ain, int lda,
                           const __half* __restrict__ W, int ldw,
                           const float* __restrict__ bias,
                           float* __restrict__ Cbase, int ldc, size_t zstride,
                           int N, int Klen, int tx_n, int nsplit)
{
    __half (*Asm)[STAGE_H] = (__half(*)[STAGE_H])sm;
    __half (*Bsm)[STAGE_H] = (__half(*)[STAGE_H])(sm + 2 * STAGE_H * 2);

    const int tid  = threadIdx.x;
    const int wid  = tid >> 5;
    const int lane = tid & 31;
    const int wm   = wid & 3;
    const int wn   = wid >> 2;
    const int g    = lane >> 2;
    const int c    = lane & 3;
    const int m0   = wm * 32;
    const int n0   = wn * 64;

    const int cr = tid >> 1;
    const int ck = (tid & 1) * 16;
    const uint32_t smA = smem_u32(Asm);
    const uint32_t smB = smem_u32(Bsm);
    const int T = Klen / BKH;
    const int ntilesM = MROWS / BM;          // 32
    const int total = tx_n * ntilesM * nsplit;

    for (int tile = blockIdx.x; tile < total; tile += GRID) {
        const int bx = tile % tx_n;
        const int by = (tile / tx_n) % ntilesM;
        const int bz = tile / (tx_n * ntilesM);
        const int row0 = by * BM;
        const int col0 = bx * BN;
        const int kofs = bz * Klen;
        float* C = Cbase + (size_t)bz * zstride;
        const int bvalid = (col0 + cr) < N ? 16 : 0;

        auto issue = [&](int t) {
            if (t < T) {
                const __half* Ap = Ain + (size_t)(row0 + cr) * lda + kofs + t * BKH + ck;
                uint32_t da = smA + ((t & 1) * STAGE_H + cr * SLDH + ck) * 2;
                cpasync16(da,      Ap,     16);
                cpasync16(da + 16, Ap + 8, 16);
                const __half* Wp = W + (size_t)(col0 + cr) * ldw + kofs + t * BKH + ck;
                uint32_t db = smB + ((t & 1) * STAGE_H + cr * SLDH + ck) * 2;
                cpasync16(db,      Wp,     bvalid);
                cpasync16(db + 16, Wp + 8, bvalid);
            }
        };

        issue(0); CP_COMMIT();

        float acc[2][8][4];
#pragma unroll
        for (int mi = 0; mi < 2; mi++)
#pragma unroll
            for (int ni = 0; ni < 8; ni++)
#pragma unroll
                for (int e = 0; e < 4; e++) acc[mi][ni][e] = 0.f;

        for (int t = 0; t < T; t++) {
            issue(t + 1);
            CP_COMMIT();
            CP_WAIT(1);
            __syncthreads();

            const __half* As = Asm[t & 1];
            const __half* Bs = Bsm[t & 1];

#pragma unroll
            for (int ks = 0; ks < 2; ks++) {
                const int kb = ks * 16;
                uint32_t a[2][4], b[8][2];
#pragma unroll
                for (int mi = 0; mi < 2; mi++) {
                    const int r = m0 + mi * 16 + g;
                    a[mi][0] = *(const uint32_t*)&As[(r    ) * SLDH + kb + 2 * c];
                    a[mi][1] = *(const uint32_t*)&As[(r + 8) * SLDH + kb + 2 * c];
                    a[mi][2] = *(const uint32_t*)&As[(r    ) * SLDH + kb + 2 * c + 8];
                    a[mi][3] = *(const uint32_t*)&As[(r + 8) * SLDH + kb + 2 * c + 8];
                }
#pragma unroll
                for (int ni = 0; ni < 8; ni++) {
                    const int r = n0 + ni * 8 + g;
                    b[ni][0] = *(const uint32_t*)&Bs[r * SLDH + kb + 2 * c];
                    b[ni][1] = *(const uint32_t*)&Bs[r * SLDH + kb + 2 * c + 8];
                }
#pragma unroll
                for (int mi = 0; mi < 2; mi++)
#pragma unroll
                    for (int ni = 0; ni < 8; ni++)
                        mma_f16(acc[mi][ni], a[mi], b[ni]);
            }
            __syncthreads();
        }

#pragma unroll
        for (int mi = 0; mi < 2; mi++) {
#pragma unroll
            for (int ni = 0; ni < 8; ni++) {
                const int colb = col0 + n0 + ni * 8;
                if (colb < N) {
                    const int cc = colb + c * 2;
#pragma unroll
                    for (int hf = 0; hf < 2; hf++) {
                        const int r = row0 + m0 + mi * 16 + g + hf * 8;
                        float2 v = make_float2(acc[mi][ni][hf * 2],
                                               acc[mi][ni][hf * 2 + 1]);
                        if (bias) { v.x += bias[cc]; v.y += bias[cc + 1]; }
                        *(float2*)(C + (size_t)r * ldc + cc) = v;
                    }
                }
            }
        }
    }
}

// ---------------------------------------------------------------------------
// Phase: residual reduce + LayerNorm (warp-per-row)
// ---------------------------------------------------------------------------
__device__ void rln_phase(const float* part, size_t zstride, int nz,
                          const float* resid, const float* w, const float* b,
                          float* h, __half* xnh)
{
    for (int grp = blockIdx.x; grp < MROWS / 8; grp += GRID) {
        const int row  = grp * 8 + (threadIdx.x >> 5);
        const int lane = threadIdx.x & 31;
        const size_t base = (size_t)row * DMODEL;

        float v[8];
        float s = 0.f, ss = 0.f;
#pragma unroll
        for (int i = 0; i < 8; i++) {
            const int c = lane + i * 32;
            float t = resid[base + c];
            for (int z = 0; z < nz; z++) t += part[(size_t)z * zstride + base + c];
            v[i] = t;
            s  += t;
            ss += t * t;
        }
#pragma unroll
        for (int off = 16; off > 0; off >>= 1) {
            s  += __shfl_xor_sync(0xffffffffu, s,  off);
            ss += __shfl_xor_sync(0xffffffffu, ss, off);
        }
        const float mean = s * (1.f / DMODEL);
        const float var  = ss * (1.f / DMODEL) - mean * mean;
        const float rstd = rsqrtf(var + LN_EPS);
#pragma unroll
        for (int i = 0; i < 8; i++) {
            const int c = lane + i * 32;
            if (nz) h[base + c] = v[i];
            if (xnh) xnh[base + c] = __float2half_rn((v[i] - mean) * rstd * w[c] + b[c]);
        }
    }
}

// ---------------------------------------------------------------------------
// Phase: causal depthwise conv + SiLU
// ---------------------------------------------------------------------------
__device__ void conv_phase(const float* xz, const float* cw, const float* cb,
                           float* u, __half* uh)
{
    for (int idx = blockIdx.x * NTHREADS + threadIdx.x; idx < MROWS * DINNER;
         idx += GRID * NTHREADS) {
        int d = idx & (DINNER - 1);
        int t = (idx >> 9) & (SEQ - 1);
        int b = idx >> 18;

        const float* base = xz + (size_t)(b * SEQ) * (2 * DINNER) + d;
        float acc = cb[d];
#pragma unroll
        for (int k = 0; k < DCONV; k++) {
            int tt = t - (DCONV - 1) + k;
            if (tt >= 0) acc += base[(size_t)tt * (2 * DINNER)] * cw[d * DCONV + k];
        }
        float uv = acc / (1.f + __expf(-acc));
        u[idx]  = uv;
        uh[idx] = __float2half_rn(uv);
    }
}

// ---------------------------------------------------------------------------
// Phase: split-K(4) reduce + dt projection + softplus (2 rows per iteration)
// ---------------------------------------------------------------------------
__device__ void rdt_phase(char* sm, const float* part, size_t zstride,
                          const float* dtw, const float* dtb,
                          float* dbl, float* dt)
{
    float (*bc)[48] = (float(*)[48])sm;
    const int sub = threadIdx.x >> 7;      // 0/1
    const int t   = threadIdx.x & 127;

    for (int r0 = blockIdx.x * 2; r0 < MROWS; r0 += GRID * 2) {
        const int r = r0 + sub;
        if (t < 48) {
            const size_t idx = (size_t)r * 48 + t;
            float v = part[idx] + part[zstride + idx]
                    + part[2 * zstride + idx] + part[3 * zstride + idx];
            bc[sub][t] = v;
            dbl[idx] = v;
        }
        __syncthreads();
#pragma unroll
        for (int dd = 0; dd < 4; dd++) {
            const int d = t + dd * 128;
            const float4* wp = (const float4*)(dtw + d * DTRANK);
            float acc = dtb[d];
#pragma unroll
            for (int q = 0; q < 4; q++) {
                float4 w4 = wp[q];
                acc += bc[sub][4*q+0]*w4.x + bc[sub][4*q+1]*w4.y
                     + bc[sub][4*q+2]*w4.z + bc[sub][4*q+3]*w4.w;
            }
            dt[(size_t)r * DINNER + d] = (acc > 20.f) ? acc : log1pf(__expf(acc));
        }
        __syncthreads();
    }
}

// ---------------------------------------------------------------------------
// Phase: selective scan (R13-proven body; grid == 256 CTAs exactly)
// ---------------------------------------------------------------------------
#define TC 32
#define SSTAGE 3072

__device__ void scan_phase(char* sm,
                           const float* dt, const float* u,
                           const float* dbl, const float* xz,
                           const float* A_log, const float* Dvec, __half* yh)
{
    float (*stage)[SSTAGE] = (float(*)[SSTAGE])sm;

    const int tid = threadIdx.x;
    const int p   = tid >> 4;
    const int s   = tid & 15;
    const int b   = blockIdx.x >> 5;
    const int d0  = (blockIdx.x & 31) * 16;
    const int d   = d0 + p;

    const uint32_t smBase = smem_u32(stage);
    const size_t rowbase = (size_t)b * SEQ;

    auto load_chunk = [&](int c) {
        if (c >= SEQ / TC) return;
        const int t0 = c * TC;
        const uint32_t dst0 = smBase + (c & 1) * SSTAGE * 4;
#pragma unroll
        for (int k = 0; k < 3; k++) {
            const int o = tid + k * 256;
            const float* src;
            int soff;
            if (o < 128) {
                const int t = o >> 2, q = o & 3;
                src  = dt + (rowbase + t0 + t) * DINNER + d0 + q * 4;
                soff = t * 16 + q * 4;
            } else if (o < 256) {
                const int o2 = o - 128;
                const int t = o2 >> 2, q = o2 & 3;
                src  = u + (rowbase + t0 + t) * DINNER + d0 + q * 4;
                soff = 512 + t * 16 + q * 4;
            } else if (o < 384) {
                const int o2 = o - 256;
                const int t = o2 >> 2, q = o2 & 3;
                src  = xz + (rowbase + t0 + t) * (2 * DINNER) + DINNER + d0 + q * 4;
                soff = 1024 + t * 16 + q * 4;
            } else {
                const int o2 = o - 384;
                const int t = o2 / 12, q = o2 % 12;
                src  = dbl + (rowbase + t0 + t) * 48 + q * 4;
                soff = 1536 + t * 48 + q * 4;
            }
            cpasync16(dst0 + soff * 4, src, 16);
        }
    };

    const float A  = -__expf(A_log[d * DSTATE + s]);
    const float Dp = Dvec[d];
    float h = 0.f;

    __half* y_p = yh + rowbase * DINNER + d;

    load_chunk(0); CP_COMMIT();

    for (int c = 0; c < SEQ / TC; c++) {
        load_chunk(c + 1);
        CP_COMMIT();
        CP_WAIT(1);
        __syncthreads();

        const float* st = stage[c & 1];
        const int t0 = c * TC;

#pragma unroll 4
        for (int tt = 0; tt < TC; tt++) {
            float dtv = st[tt * 16 + p];
            float uv  = st[512 + tt * 16 + p];
            float Bv  = st[1536 + tt * 48 + 16 + s];
            float Cv  = st[1536 + tt * 48 + 32 + s];

            h = __expf(dtv * A) * h + dtv * uv * Bv;
            float yv = h * Cv;
            yv += __shfl_xor_sync(0xffffffffu, yv, 8);
            yv += __shfl_xor_sync(0xffffffffu, yv, 4);
            yv += __shfl_xor_sync(0xffffffffu, yv, 2);
            yv += __shfl_xor_sync(0xffffffffu, yv, 1);

            if (s == 0) {
                float zv  = st[1024 + tt * 16 + p];
                float out = (yv + uv * Dp) * (zv / (1.f + __expf(-zv)));
                y_p[(size_t)(t0 + tt) * DINNER] = __float2half_rn(out);
            }
        }
        __syncthreads();
    }
}

// ---------------------------------------------------------------------------
// Phase: fused head (blocks 0..7)
// ---------------------------------------------------------------------------
__device__ void head_phase(char* sm, const float* h,
                           const float* w1, const float* b1,
                           const float* w2, const float* b2, float* out)
{
    if (blockIdx.x >= BATCH) return;
    float* hs  = (float*)sm;
    float* red = hs + DMODEL;
    const int b = blockIdx.x;
    const int n = threadIdx.x;

    hs[n] = h[((size_t)b * SEQ + (SEQ - 1)) * DMODEL + n];
    __syncthreads();

    const float4* wp = (const float4*)(w1 + (size_t)n * DMODEL);
    float acc = b1[n];
#pragma unroll 8
    for (int k = 0; k < DMODEL / 4; k++) {
        float4 w4 = wp[k];
        acc += hs[4*k+0]*w4.x + hs[4*k+1]*w4.y + hs[4*k+2]*w4.z + hs[4*k+3]*w4.w;
    }
    float t1 = fmaxf(acc, 0.f);

    float v = t1 * w2[n];
#pragma unroll
    for (int off = 16; off > 0; off >>= 1)
        v += __shfl_xor_sync(0xffffffffu, v, off);
    if ((n & 31) == 0) red[n >> 5] = v;
    __syncthreads();
    if (n < 32) {
        float r = (n < 8) ? red[n] : 0.f;
#pragma unroll
        for (int off = 4; off > 0; off >>= 1)
            r += __shfl_xor_sync(0xffffffffu, r, off);
        if (n == 0) out[b] = r + b2[0];
    }
}

// ---------------------------------------------------------------------------
// The megakernel
// ---------------------------------------------------------------------------
__global__ __launch_bounds__(NTHREADS, 2)
void mega_kernel(MegaArgs A)
{
    __shared__ __align__(16) char sm[4 * STAGE_H * 2];   // 40960 B

    // P0: convert weights/inputs to fp16
    cvt_phase(A);
    gbar();

    // P1: input projection (N=256, K=32) -> 64 tiles
    gemm_phase(sm, A.wh + X_H, INPUT_DIM, A.wh + IPW_H, INPUT_DIM, A.ipb,
               A.h, DMODEL, 0, DMODEL, INPUT_DIM, 2, 1);
    gbar();

    // P2: initial LN
    rln_phase(nullptr, 0, 0, A.h, A.lnw, A.lnb, A.h, A.xnh);
    gbar();

#pragma unroll 1
    for (int l = 0; l < NLAYERS; l++) {
        // in_proj (N=1024, K=256) -> 256 tiles
        gemm_phase(sm, A.xnh, DMODEL, A.wh + INW_H + (size_t)l * 2 * DINNER * DMODEL,
                   DMODEL, nullptr, A.xz, 2 * DINNER, 0, 2 * DINNER, DMODEL, 8, 1);
        gbar();

        // conv + silu
        conv_phase(A.xz, A.cw + l * DINNER * DCONV, A.cb + l * DINNER, A.u, A.uh);
        gbar();

        // x_proj (N=48, K=512) split-K=4 -> 128 tiles
        gemm_phase(sm, A.uh, DINNER, A.wh + XPW_H + (size_t)l * 48 * DINNER,
                   DINNER, nullptr, A.part, 48, (size_t)MROWS * 48, 48,
                   DINNER / 4, 1, 4);
        gbar();

        // reduce + dt
        rdt_phase(sm, A.part, (size_t)MROWS * 48,
                  A.dtw + (size_t)l * DINNER * DTRANK, A.dtb + l * DINNER,
                  A.dbl, A.dt);
        gbar();

        // selective scan
        scan_phase(sm, A.dt, A.u, A.dbl, A.xz,
                   A.alog + (size_t)l * DINNER * DSTATE, A.dvec + l * DINNER, A.yh);
        gbar();

        // out_proj (N=256, K=512) split-K=2 -> 128 tiles
        gemm_phase(sm, A.yh, DINNER, A.wh + OPW_H + (size_t)l * DMODEL * DINNER,
                   DINNER, nullptr, A.part, DMODEL, (size_t)MROWS * DMODEL,
                   DMODEL, DINNER / 2, 2, 2);
        gbar();

        // residual reduce + LN (skip xn on last layer)
        const bool last = (l + 1 == NLAYERS);
        rln_phase(A.part, (size_t)MROWS * DMODEL, 2, A.h,
                  A.lnw + (last ? l : l + 1) * DMODEL,
                  A.lnb + (last ? l : l + 1) * DMODEL,
                  A.h, last ? nullptr : A.xnh);
        gbar();
    }

    // head
    head_phase(sm, A.h, A.hw1, A.hb1, A.hw2, A.hb2, A.out);
}

// ---------------------------------------------------------------------------
// Host launcher: ONE kernel launch
// ---------------------------------------------------------------------------
extern "C" void kernel_launch(void* const* d_in, const int* in_sizes, int n_in,
                              void* d_out, int out_size)
{
    MegaArgs A;
    A.x    = (const float*)d_in[0];
    A.ipw  = (const float*)d_in[1];
    A.ipb  = (const float*)d_in[2];
    A.lnw  = (const float*)d_in[3];
    A.lnb  = (const float*)d_in[4];
    A.inw  = (const float*)d_in[5];
    A.cw   = (const float*)d_in[6];
    A.cb   = (const float*)d_in[7];
    A.xpw  = (const float*)d_in[8];
    A.dtw  = (const float*)d_in[9];
    A.dtb  = (const float*)d_in[10];
    A.alog = (const float*)d_in[11];
    A.dvec = (const float*)d_in[12];
    A.opw  = (const float*)d_in[13];
    A.hw1  = (const float*)d_in[14];
    A.hb1  = (const float*)d_in[15];
    A.hw2  = (const float*)d_in[16];
    A.hb2  = (const float*)d_in[17];
    A.out  = (float*)d_out;

    cudaGetSymbolAddress((void**)&A.h,    g_h);
    cudaGetSymbolAddress((void**)&A.xnh,  g_xnh);
    cudaGetSymbolAddress((void**)&A.xz,   g_xz);
    cudaGetSymbolAddress((void**)&A.u,    g_u);
    cudaGetSymbolAddress((void**)&A.uh,   g_uh);
    cudaGetSymbolAddress((void**)&A.dbl,  g_dbl);
    cudaGetSymbolAddress((void**)&A.dt,   g_dt);
    cudaGetSymbolAddress((void**)&A.yh,   g_yh);
    cudaGetSymbolAddress((void**)&A.part, g_part);
    cudaGetSymbolAddress((void**)&A.wh,   g_wh);

    mega_kernel<<<GRID, NTHREADS>>>(A);
}

// round 15
// speedup vs baseline: 1.0756x; 1.0756x over previous
#include <cuda_runtime.h>
#include <cuda_fp16.h>
#include <cstdint>

// ---------------------------------------------------------------------------
// Model constants
// ---------------------------------------------------------------------------
#define BATCH     8
#define SEQ       512
#define INPUT_DIM 32
#define DMODEL    256
#define NLAYERS   4
#define DSTATE    16
#define DCONV     4
#define DINNER    512
#define DTRANK    16
#define MROWS     (BATCH*SEQ)    // 4096
#define LN_EPS    1e-5f

// ---------------------------------------------------------------------------
// Device scratch
// ---------------------------------------------------------------------------
__device__ float  g_h   [MROWS * DMODEL];
__device__ __half g_xnh [MROWS * DMODEL];
__device__ __half g_xzh [MROWS * 2 * DINNER];    // fp16 now
__device__ __half g_uh  [MROWS * DINNER];
__device__ float  g_dbl [MROWS * 48];
__device__ float  g_dt  [MROWS * DINNER];
__device__ __half g_yh  [MROWS * DINNER];
__device__ float  g_part[2 * MROWS * DMODEL];

// half scratch for converted inputs/weights (offsets in halves)
#define X_H    0
#define IPW_H  131072
#define INW_H  139264
#define XPW_H  1187840
#define OPW_H  1286144
#define WH_TOTAL 1810432
__device__ __half g_wh[WH_TOTAL];

// ---------------------------------------------------------------------------
// PTX helpers
// ---------------------------------------------------------------------------
__device__ __forceinline__ void mma_f16(float* cc, const uint32_t* a, const uint32_t* b) {
    asm volatile("mma.sync.aligned.m16n8k16.row.col.f32.f16.f16.f32 "
                 "{%0,%1,%2,%3}, {%4,%5,%6,%7}, {%8,%9}, {%0,%1,%2,%3};"
                 : "+f"(cc[0]), "+f"(cc[1]), "+f"(cc[2]), "+f"(cc[3])
                 : "r"(a[0]), "r"(a[1]), "r"(a[2]), "r"(a[3]),
                   "r"(b[0]), "r"(b[1]));
}

__device__ __forceinline__ uint32_t smem_u32(const void* p) {
    uint32_t a;
    asm("{ .reg .u64 t; cvta.to.shared.u64 t, %1; cvt.u32.u64 %0, t; }"
        : "=r"(a) : "l"(p));
    return a;
}

__device__ __forceinline__ void cpasync16(uint32_t dst, const void* src, int src_sz) {
    asm volatile("cp.async.cg.shared.global [%0], [%1], 16, %2;"
                 :: "r"(dst), "l"(src), "r"(src_sz) : "memory");
}
#define CP_COMMIT()  asm volatile("cp.async.commit_group;" ::: "memory")
#define CP_WAIT(n)   asm volatile("cp.async.wait_group %0;" :: "n"(n) : "memory")

// ---------------------------------------------------------------------------
// fp16 mma.sync NT GEMM, BK=32, cp.async double buffer (40KB static SMEM).
// Output fp32 (C) or fp16 (Ch) — exactly one non-null.
// ---------------------------------------------------------------------------
#define BM 128
#define BN 128
#define BKH 32
#define SLDH 40
#define STAGE_H (BM * SLDH)    // 5120 halves

__global__ __launch_bounds__(256)
void gemm_h(const __half* __restrict__ A, int lda,
            const __half* __restrict__ W, int ldw,
            const float* __restrict__ bias,
            float* __restrict__ C, __half* __restrict__ Ch,
            int ldc, size_t zstride, int N, int Klen)
{
    __shared__ __half Asm[2][STAGE_H];
    __shared__ __half Bsm[2][STAGE_H];

    const int tid  = threadIdx.x;
    const int wid  = tid >> 5;
    const int lane = tid & 31;
    const int wm   = wid & 3;
    const int wn   = wid >> 2;
    const int g    = lane >> 2;
    const int c    = lane & 3;
    const int m0   = wm * 32;
    const int n0   = wn * 64;

    const int row0 = blockIdx.y * BM;
    const int col0 = blockIdx.x * BN;
    const int kofs = blockIdx.z * Klen;
    if (C) C += (size_t)blockIdx.z * zstride;

    const int cr = tid >> 1;
    const int ck = (tid & 1) * 16;
    const int bvalid = (col0 + cr) < N ? 16 : 0;

    const uint32_t smA = smem_u32(Asm);
    const uint32_t smB = smem_u32(Bsm);
    const int T = Klen / BKH;

    auto issue = [&](int t) {
        if (t < T) {
            const __half* Ap = A + (size_t)(row0 + cr) * lda + kofs + t * BKH + ck;
            uint32_t da = smA + ((t & 1) * STAGE_H + cr * SLDH + ck) * 2;
            cpasync16(da,      Ap,     16);
            cpasync16(da + 16, Ap + 8, 16);
            const __half* Wp = W + (size_t)(col0 + cr) * ldw + kofs + t * BKH + ck;
            uint32_t db = smB + ((t & 1) * STAGE_H + cr * SLDH + ck) * 2;
            cpasync16(db,      Wp,     bvalid);
            cpasync16(db + 16, Wp + 8, bvalid);
        }
    };

    issue(0); CP_COMMIT();

    float acc[2][8][4];
#pragma unroll
    for (int mi = 0; mi < 2; mi++)
#pragma unroll
        for (int ni = 0; ni < 8; ni++)
#pragma unroll
            for (int e = 0; e < 4; e++) acc[mi][ni][e] = 0.f;

    for (int t = 0; t < T; t++) {
        issue(t + 1);
        CP_COMMIT();
        CP_WAIT(1);
        __syncthreads();

        const __half* As = Asm[t & 1];
        const __half* Bs = Bsm[t & 1];

#pragma unroll
        for (int ks = 0; ks < 2; ks++) {
            const int kb = ks * 16;
            uint32_t a[2][4], b[8][2];
#pragma unroll
            for (int mi = 0; mi < 2; mi++) {
                const int r = m0 + mi * 16 + g;
                a[mi][0] = *(const uint32_t*)&As[(r    ) * SLDH + kb + 2 * c];
                a[mi][1] = *(const uint32_t*)&As[(r + 8) * SLDH + kb + 2 * c];
                a[mi][2] = *(const uint32_t*)&As[(r    ) * SLDH + kb + 2 * c + 8];
                a[mi][3] = *(const uint32_t*)&As[(r + 8) * SLDH + kb + 2 * c + 8];
            }
#pragma unroll
            for (int ni = 0; ni < 8; ni++) {
                const int r = n0 + ni * 8 + g;
                b[ni][0] = *(const uint32_t*)&Bs[r * SLDH + kb + 2 * c];
                b[ni][1] = *(const uint32_t*)&Bs[r * SLDH + kb + 2 * c + 8];
            }
#pragma unroll
            for (int mi = 0; mi < 2; mi++)
#pragma unroll
                for (int ni = 0; ni < 8; ni++)
                    mma_f16(acc[mi][ni], a[mi], b[ni]);
        }
        __syncthreads();
    }

    // ---- epilogue ----
#pragma unroll
    for (int mi = 0; mi < 2; mi++) {
#pragma unroll
        for (int ni = 0; ni < 8; ni++) {
            const int colb = col0 + n0 + ni * 8;
            if (colb < N) {
                const int cc = colb + c * 2;
#pragma unroll
                for (int hf = 0; hf < 2; hf++) {
                    const int r = row0 + m0 + mi * 16 + g + hf * 8;
                    float2 v = make_float2(acc[mi][ni][hf * 2],
                                           acc[mi][ni][hf * 2 + 1]);
                    if (bias) { v.x += bias[cc]; v.y += bias[cc + 1]; }
                    if (C)  *(float2*)(C + (size_t)r * ldc + cc) = v;
                    else    *(__half2*)(Ch + (size_t)r * ldc + cc) =
                                __floats2half2_rn(v.x, v.y);
                }
            }
        }
    }
}

// ---------------------------------------------------------------------------
// Merged fp32->fp16 conversion of all inputs/weights into g_wh
// ---------------------------------------------------------------------------
__global__ __launch_bounds__(256)
void cvt_all(const float* __restrict__ x,   const float* __restrict__ ipw,
             const float* __restrict__ inw, const float* __restrict__ xpw,
             const float* __restrict__ opw, __half* __restrict__ dst)
{
    int i = (blockIdx.x * blockDim.x + threadIdx.x) * 8;
    if (i >= WH_TOTAL) return;
    const float* src;
    int off;
    if      (i < IPW_H) { src = x;   off = i - X_H;   }
    else if (i < INW_H) { src = ipw; off = i - IPW_H; }
    else if (i < XPW_H) { src = inw; off = i - INW_H; }
    else if (i < OPW_H) { src = xpw; off = i - XPW_H; }
    else                { src = opw; off = i - OPW_H; }
    float4 v0 = *(const float4*)(src + off);
    float4 v1 = *(const float4*)(src + off + 4);
    __half2* d2 = (__half2*)(dst + i);
    d2[0] = __floats2half2_rn(v0.x, v0.y);
    d2[1] = __floats2half2_rn(v0.z, v0.w);
    d2[2] = __floats2half2_rn(v1.x, v1.y);
    d2[3] = __floats2half2_rn(v1.z, v1.w);
}

// ---------------------------------------------------------------------------
// Fused residual reduce + LayerNorm, warp-per-row
// ---------------------------------------------------------------------------
__global__ __launch_bounds__(256)
void reduce_ln_kernel(const float* __restrict__ part, size_t zstride, int nz,
                      const float* __restrict__ resid,
                      const float* __restrict__ w, const float* __restrict__ b,
                      float* __restrict__ h, __half* __restrict__ xnh)
{
    const int row  = blockIdx.x * 8 + (threadIdx.x >> 5);
    const int lane = threadIdx.x & 31;
    const size_t base = (size_t)row * DMODEL;

    float v[8];
    float s = 0.f, ss = 0.f;
#pragma unroll
    for (int i = 0; i < 8; i++) {
        const int c = lane + i * 32;
        float t = resid[base + c];
        for (int z = 0; z < nz; z++) t += part[(size_t)z * zstride + base + c];
        v[i] = t;
        s  += t;
        ss += t * t;
    }
#pragma unroll
    for (int off = 16; off > 0; off >>= 1) {
        s  += __shfl_xor_sync(0xffffffffu, s,  off);
        ss += __shfl_xor_sync(0xffffffffu, ss, off);
    }
    const float mean = s * (1.f / DMODEL);
    const float var  = ss * (1.f / DMODEL) - mean * mean;
    const float rstd = rsqrtf(var + LN_EPS);

#pragma unroll
    for (int i = 0; i < 8; i++) {
        const int c = lane + i * 32;
        if (nz) h[base + c] = v[i];
        if (xnh) xnh[base + c] = __float2half_rn((v[i] - mean) * rstd * w[c] + b[c]);
    }
}

// ---------------------------------------------------------------------------
// Fused: dbl row = sum of 4 split-K partials; dt = softplus(dbl[:16]@dtw^T+b)
// ---------------------------------------------------------------------------
__global__ __launch_bounds__(128)
void reduce_dt_kernel(const float* __restrict__ part, size_t zstride,
                      const float* __restrict__ dtw, const float* __restrict__ dtb,
                      float* __restrict__ dbl, float* __restrict__ dt)
{
    __shared__ float bc[48];
    const int r = blockIdx.x;
    const int t = threadIdx.x;

    if (t < 48) {
        const size_t idx = (size_t)r * 48 + t;
        float v = part[idx] + part[zstride + idx]
                + part[2 * zstride + idx] + part[3 * zstride + idx];
        bc[t] = v;
        dbl[idx] = v;
    }
    __syncthreads();

#pragma unroll
    for (int dd = 0; dd < 4; dd++) {
        const int d = t + dd * 128;
        const float4* wp = (const float4*)(dtw + d * DTRANK);
        float acc = dtb[d];
#pragma unroll
        for (int q = 0; q < 4; q++) {
            float4 w4 = wp[q];
            acc += bc[4*q+0]*w4.x + bc[4*q+1]*w4.y + bc[4*q+2]*w4.z + bc[4*q+3]*w4.w;
        }
        dt[(size_t)r * DINNER + d] = (acc > 20.f) ? acc : log1pf(__expf(acc));
    }
}

// ---------------------------------------------------------------------------
// Causal depthwise conv (width 4) + SiLU; reads fp16 xz, writes fp16 uh
// ---------------------------------------------------------------------------
__global__ __launch_bounds__(256)
void conv_silu_kernel(const __half* __restrict__ xzh,
                      const float* __restrict__ cw, const float* __restrict__ cb,
                      __half* __restrict__ uh)
{
    int idx = blockIdx.x * blockDim.x + threadIdx.x;
    if (idx >= MROWS * DINNER) return;
    int d = idx & (DINNER - 1);
    int t = (idx >> 9) & (SEQ - 1);
    int b = idx >> 18;

    const __half* base = xzh + (size_t)(b * SEQ) * (2 * DINNER) + d;
    float acc = cb[d];
#pragma unroll
    for (int k = 0; k < DCONV; k++) {
        int tt = t - (DCONV - 1) + k;
        if (tt >= 0)
            acc += __half2float(base[(size_t)tt * (2 * DINNER)]) * cw[d * DCONV + k];
    }
    uh[idx] = __float2half_rn(acc / (1.f + __expf(-acc)));
}

// ---------------------------------------------------------------------------
// Selective scan v5: mixed-precision staged chunks (TC=32, double buffer).
// Stage bytes: DT f32 [0,2048) | U h16 [2048,3072) | Z h16 [3072,4096)
//              | BC f32 [4096,10240).  10240 B/stage.
// cp.async 16B chunks per stage: dt 128, u 64, z 64, bc 384 -> 640 (2.5/thr)
// ---------------------------------------------------------------------------
#define TC 32
#define SB_DT 0
#define SB_U  2048
#define SB_Z  3072
#define SB_BC 4096
#define SSTAGE_B 10240

__global__ __launch_bounds__(256)
void scan_kernel(const float* __restrict__ dt, const __half* __restrict__ uh,
                 const float* __restrict__ dbl, const __half* __restrict__ xzh,
                 const float* __restrict__ A_log, const float* __restrict__ Dvec,
                 __half* __restrict__ yh)
{
    __shared__ __align__(16) char stage[2][SSTAGE_B];

    const int tid = threadIdx.x;
    const int p   = tid >> 4;
    const int s   = tid & 15;
    const int b   = blockIdx.x >> 5;
    const int d0  = (blockIdx.x & 31) * 16;
    const int d   = d0 + p;

    const uint32_t smBase = smem_u32(stage);
    const size_t rowbase = (size_t)b * SEQ;

    auto load_chunk = [&](int c) {
        if (c >= SEQ / TC) return;
        const int t0 = c * TC;
        const uint32_t dst0 = smBase + (c & 1) * SSTAGE_B;
#pragma unroll
        for (int k = 0; k < 3; k++) {
            const int o = tid + k * 256;
            if (o >= 640) break;
            const void* src;
            int soff;
            if (o < 128) {                 // dt f32: t = o>>2, q = o&3
                const int t = o >> 2, q = o & 3;
                src  = dt + (rowbase + t0 + t) * DINNER + d0 + q * 4;
                soff = SB_DT + o * 16;
            } else if (o < 192) {          // u h16: t = i>>1, half-row = i&1
                const int i = o - 128, t = i >> 1, q = i & 1;
                src  = uh + (rowbase + t0 + t) * DINNER + d0 + q * 8;
                soff = SB_U + i * 16;
            } else if (o < 256) {          // z h16
                const int i = o - 192, t = i >> 1, q = i & 1;
                src  = xzh + (rowbase + t0 + t) * (2 * DINNER) + DINNER + d0 + q * 8;
                soff = SB_Z + i * 16;
            } else {                       // bc f32: 12 chunks per t
                const int i = o - 256, t = i / 12, q = i % 12;
                src  = dbl + (rowbase + t0 + t) * 48 + q * 4;
                soff = SB_BC + i * 16;
            }
            cpasync16(dst0 + soff, src, 16);
        }
    };

    const float A  = -__expf(A_log[d * DSTATE + s]);
    const float Dp = Dvec[d];
    float h = 0.f;

    __half* y_p = yh + rowbase * DINNER + d;

    load_chunk(0); CP_COMMIT();

    for (int c = 0; c < SEQ / TC; c++) {
        load_chunk(c + 1);
        CP_COMMIT();
        CP_WAIT(1);
        __syncthreads();

        const char* st = stage[c & 1];
        const float*  st_dt = (const float*)(st + SB_DT);
        const __half* st_u  = (const __half*)(st + SB_U);
        const __half* st_z  = (const __half*)(st + SB_Z);
        const float*  st_bc = (const float*)(st + SB_BC);
        const int t0 = c * TC;

#pragma unroll 4
        for (int tt = 0; tt < TC; tt++) {
            float dtv = st_dt[tt * 16 + p];
            float uv  = __half2float(st_u[tt * 16 + p]);
            float Bv  = st_bc[tt * 48 + 16 + s];
            float Cv  = st_bc[tt * 48 + 32 + s];

            h = __expf(dtv * A) * h + dtv * uv * Bv;
            float yv = h * Cv;
            yv += __shfl_xor_sync(0xffffffffu, yv, 8);
            yv += __shfl_xor_sync(0xffffffffu, yv, 4);
            yv += __shfl_xor_sync(0xffffffffu, yv, 2);
            yv += __shfl_xor_sync(0xffffffffu, yv, 1);

            if (s == 0) {
                float zv  = __half2float(st_z[tt * 16 + p]);
                float out = (yv + uv * Dp) * (zv / (1.f + __expf(-zv)));
                y_p[(size_t)(t0 + tt) * DINNER] = __float2half_rn(out);
            }
        }
        __syncthreads();
    }
}

// ---------------------------------------------------------------------------
// Fused head
// ---------------------------------------------------------------------------
__global__ __launch_bounds__(256)
void head_kernel(const float* __restrict__ h,
                 const float* __restrict__ w1, const float* __restrict__ b1,
                 const float* __restrict__ w2, const float* __restrict__ b2,
                 float* __restrict__ out)
{
    __shared__ float hs[DMODEL];
    __shared__ float red[8];
    const int b = blockIdx.x;
    const int n = threadIdx.x;

    hs[n] = h[((size_t)b * SEQ + (SEQ - 1)) * DMODEL + n];
    __syncthreads();

    const float4* wp = (const float4*)(w1 + (size_t)n * DMODEL);
    float acc = b1[n];
#pragma unroll 8
    for (int k = 0; k < DMODEL / 4; k++) {
        float4 w4 = wp[k];
        acc += hs[4*k+0]*w4.x + hs[4*k+1]*w4.y + hs[4*k+2]*w4.z + hs[4*k+3]*w4.w;
    }
    float t1 = fmaxf(acc, 0.f);

    float v = t1 * w2[n];
#pragma unroll
    for (int off = 16; off > 0; off >>= 1)
        v += __shfl_xor_sync(0xffffffffu, v, off);
    if ((n & 31) == 0) red[n >> 5] = v;
    __syncthreads();
    if (n < 32) {
        float r = (n < 8) ? red[n] : 0.f;
#pragma unroll
        for (int off = 4; off > 0; off >>= 1)
            r += __shfl_xor_sync(0xffffffffu, r, off);
        if (n == 0) out[b] = r + b2[0];
    }
}

// ---------------------------------------------------------------------------
// Host launcher
// ---------------------------------------------------------------------------
extern "C" void kernel_launch(void* const* d_in, const int* in_sizes, int n_in,
                              void* d_out, int out_size)
{
    const float* x            = (const float*)d_in[0];
    const float* input_proj_w = (const float*)d_in[1];
    const float* input_proj_b = (const float*)d_in[2];
    const float* ln_w         = (const float*)d_in[3];
    const float* ln_b         = (const float*)d_in[4];
    const float* in_proj_w    = (const float*)d_in[5];
    const float* conv_w       = (const float*)d_in[6];
    const float* conv_b       = (const float*)d_in[7];
    const float* x_proj_w     = (const float*)d_in[8];
    const float* dt_proj_w    = (const float*)d_in[9];
    const float* dt_proj_b    = (const float*)d_in[10];
    const float* A_log        = (const float*)d_in[11];
    const float* Dvec         = (const float*)d_in[12];
    const float* out_proj_w   = (const float*)d_in[13];
    const float* head_w1      = (const float*)d_in[14];
    const float* head_b1      = (const float*)d_in[15];
    const float* head_w2      = (const float*)d_in[16];
    const float* head_b2      = (const float*)d_in[17];
    float* out = (float*)d_out;

    float  *p_h, *p_dbl, *p_dt, *p_part;
    __half *p_xnh, *p_xzh, *p_uh, *p_yh, *p_wh;
    cudaGetSymbolAddress((void**)&p_h,    g_h);
    cudaGetSymbolAddress((void**)&p_xnh,  g_xnh);
    cudaGetSymbolAddress((void**)&p_xzh,  g_xzh);
    cudaGetSymbolAddress((void**)&p_uh,   g_uh);
    cudaGetSymbolAddress((void**)&p_dbl,  g_dbl);
    cudaGetSymbolAddress((void**)&p_dt,   g_dt);
    cudaGetSymbolAddress((void**)&p_yh,   g_yh);
    cudaGetSymbolAddress((void**)&p_part, g_part);
    cudaGetSymbolAddress((void**)&p_wh,   g_wh);

    // convert all fp32 operands to fp16 scratch
    cvt_all<<<(WH_TOTAL / 8 + 255) / 256, 256>>>(
        x, input_proj_w, in_proj_w, x_proj_w, out_proj_w, p_wh);

    // input projection  (N=256, K=32) -> fp32 h
    gemm_h<<<dim3(DMODEL/BN, MROWS/BM, 1), 256>>>(
        p_wh + X_H, INPUT_DIM, p_wh + IPW_H, INPUT_DIM, input_proj_b,
        p_h, nullptr, DMODEL, 0, DMODEL, INPUT_DIM);

    // LN of initial h
    reduce_ln_kernel<<<MROWS / 8, 256>>>(nullptr, 0, 0, p_h,
                                         ln_w, ln_b, p_h, p_xnh);

    for (int l = 0; l < NLAYERS; l++) {
        // in_proj  (N=1024, K=256) -> fp16 xzh
        gemm_h<<<dim3((2*DINNER)/BN, MROWS/BM, 1), 256>>>(
            p_xnh, DMODEL, p_wh + INW_H + (size_t)l * 2 * DINNER * DMODEL, DMODEL,
            nullptr, nullptr, p_xzh, 2 * DINNER, 0, 2 * DINNER, DMODEL);

        // conv + silu -> uh (fp16)
        conv_silu_kernel<<<(MROWS * DINNER) / 256, 256>>>(
            p_xzh, conv_w + l * DINNER * DCONV, conv_b + l * DINNER, p_uh);

        // x_proj (N=48, K=512), split-K=4 -> fp32 partials
        gemm_h<<<dim3(1, MROWS/BM, 4), 256>>>(
            p_uh, DINNER, p_wh + XPW_H + (size_t)l * 48 * DINNER, DINNER,
            nullptr, p_part, nullptr, 48, (size_t)MROWS * 48, 48, DINNER / 4);

        // fused split-K reduce + dt projection + softplus
        reduce_dt_kernel<<<MROWS, 128>>>(
            p_part, (size_t)MROWS * 48,
            dt_proj_w + (size_t)l * DINNER * DTRANK, dt_proj_b + l * DINNER,
            p_dbl, p_dt);

        // selective scan (mixed-precision staged)
        scan_kernel<<<256, 256>>>(
            p_dt, p_uh, p_dbl, p_xzh,
            A_log + (size_t)l * DINNER * DSTATE, Dvec + l * DINNER, p_yh);

        // out_proj (N=256, K=512) split-K=2 -> fp32 partials
        gemm_h<<<dim3(DMODEL/BN, MROWS/BM, 2), 256>>>(
            p_yh, DINNER, p_wh + OPW_H + (size_t)l * DMODEL * DINNER, DINNER,
            nullptr, p_part, nullptr, DMODEL, (size_t)MROWS * DMODEL,
            DMODEL, DINNER / 2);

        // fused residual reduce + LN (skip xn on last layer)
        const bool last = (l + 1 == NLAYERS);
        reduce_ln_kernel<<<MROWS / 8, 256>>>(
            p_part, (size_t)MROWS * DMODEL, 2, p_h,
            ln_w + (last ? l : l + 1) * DMODEL,
            ln_b + (last ? l : l + 1) * DMODEL,
            p_h, last ? nullptr : p_xnh);
    }

    // fused head
    head_kernel<<<BATCH, 256>>>(p_h, head_w1, head_b1, head_w2, head_b2, out);
}